// round 15
// baseline (speedup 1.0000x reference)
#include <cuda_runtime.h>
#include <cuda_bf16.h>
#include <math_constants.h>
#include <cstdint>

#define N_TOTAL 32768
#define DIM     256
#define KCODES  1024
#define HW      1024
#define MARGIN  2.5e-3f
#define CANDCAP 32

// ---------------- scratch ----------------
__device__ __align__(16) uint32_t g_epack[(size_t)KCODES * 128];  // bf16x2 codes, K-major
__device__ float    g_embsq[KCODES];
__device__ int      g_idx[N_TOTAL];
__device__ double   g_partial[1024];

// ---------------- cp.async helpers ----------------
__device__ __forceinline__ void cp16(uint32_t saddr, const void* gaddr) {
    asm volatile("cp.async.cg.shared.global [%0], [%1], 16;" :: "r"(saddr), "l"(gaddr));
}
#define CP_COMMIT() asm volatile("cp.async.commit_group;" ::: "memory")
#define CP_WAIT(n)  asm volatile("cp.async.wait_group %0;" :: "n"(n) : "memory")

// order-preserving float -> u32; key = (ord(score) << 32) | idx  (min = best, ties -> min idx)
__device__ __forceinline__ unsigned long long mkkey(float s, int k) {
    unsigned u = __float_as_uint(s);
    u = (u & 0x80000000u) ? ~u : (u | 0x80000000u);
    return ((unsigned long long)u << 32) | (unsigned)k;
}

// ---------------- fused pack(e->bf16) + embsq, transpose-staged -------------
// 32 blocks x 256 threads; block handles 32 codebook rows.
// Loads coalesced (lanes sweep columns); embsq chains remain bit-exact
// sequential per row (same __fadd_rn/__fmul_rn order as before).
__global__ __launch_bounds__(256) void k_prep(const float* __restrict__ e) {
    __shared__ float sE[32][257];
    int tid = threadIdx.x;
    int r0 = blockIdx.x * 32;
#pragma unroll
    for (int i = 0; i < 32; i++) {
        int idx = tid + i * 256;
        int row = idx >> 8, c = idx & 255;
        sE[row][c] = e[(size_t)(r0 + row) * DIM + c];
    }
    __syncthreads();
    if (tid < 32) {
        float acc = 0.f;
#pragma unroll 8
        for (int c = 0; c < DIM; c++) {
            float v = sE[tid][c];
            acc = __fadd_rn(acc, __fmul_rn(v, v));
        }
        g_embsq[r0 + tid] = acc;
    }
#pragma unroll
    for (int i = 0; i < 16; i++) {
        int idx = tid + i * 256;          // 0..4095 = 32 rows * 128 pairs
        int row = idx >> 7, cp = idx & 127;
        float f0 = sE[row][2 * cp], f1 = sE[row][2 * cp + 1];
        __nv_bfloat16 h0 = __float2bfloat16_rn(f0);
        __nv_bfloat16 h1 = __float2bfloat16_rn(f1);
        g_epack[(size_t)(r0 + row) * 128 + cp] =
            ((uint32_t)__bfloat16_as_ushort(h1) << 16) | __bfloat16_as_ushort(h0);
    }
}

// ---------------- fused: staging + rowsq + HMMA + argmin + exact rescore ----
#define SA_ST     132
#define SB_OFF    (128 * SA_ST)            // 16896
#define SB_BUF    (128 * SA_ST)
#define SBK_OFF   (SB_OFF + 2 * SB_BUF)    // 50688
#define SMINW_OFF (SBK_OFF + 1024)         // 51712
#define SBEST_OFF (SMINW_OFF + 512)        // 52224
#define SCNT_OFF  (SBEST_OFF + 128)        // 52352
#define SCAND_OFF (SCNT_OFF + 128)         // 52480 : u16 [128][32] = 2048 u32
#define SAN_OFF   (SCAND_OFF + 2048)       // 54528
#define SKEY_OFF  (SAN_OFF + 128)          // 54656 (8B-aligned)
#define SOVF_OFF  (SKEY_OFF + 256)         // 54912 : [0]=count, [1..128]=rows
#define SMEM_U32  (SOVF_OFF + 132)         // 55044
#define SMEM_BYTES (SMEM_U32 * 4)          // 220176 B < 227KB opt-in

__global__ __launch_bounds__(512, 1) void k_gemm(const float* __restrict__ x,
                                                 const float* __restrict__ e) {
    extern __shared__ __align__(16) uint32_t sm[];
    uint32_t* sA   = sm;
    float*    sBk  = (float*)(sm + SBK_OFF);
    float*    sMnW = (float*)(sm + SMINW_OFF);
    float*    sBest= (float*)(sm + SBEST_OFF);
    int*      sCnt = (int*)(sm + SCNT_OFF);
    unsigned short* sCand = (unsigned short*)(sm + SCAND_OFF);
    float*    sAn  = (float*)(sm + SAN_OFF);
    unsigned long long* sKey = (unsigned long long*)(sm + SKEY_OFF);
    int*      sOvf = (int*)(sm + SOVF_OFF);

    int tid = threadIdx.x;
    int lane = tid & 31, w = tid >> 5;
    int g = lane >> 2, tg = lane & 3;
    int wm = w & 3, wn = w >> 2;
    int n0 = blockIdx.x * 128;

    uint32_t smu;
    asm("{ .reg .u64 t; cvta.to.shared.u64 t, %1; cvt.u32.u64 %0, t; }"
        : "=r"(smu) : "l"(sm));

    // kick off panel 0 -> buf0
    {
        const uint32_t* gsrc = g_epack;
#pragma unroll
        for (int i = 0; i < 8; i++) {
            int seg = tid + i * 512, code = seg >> 5, j = seg & 31;
            cp16(smu + (uint32_t)(SB_OFF + code * SA_ST + j * 4) * 4,
                 gsrc + code * 128 + j * 4);
        }
        CP_COMMIT();
    }

    for (int i = tid; i < KCODES; i += 512) sBk[i] = g_embsq[i];
    if (tid < 128) { sCnt[tid] = 0; sBest[tid] = CUDART_INF_F; }
    if (tid == 0) sOvf[0] = 0;

    // ---- A staging + rowsq; sT aliased into B buffer 1 ----
    float* sT = (float*)(sm + SB_OFF + SB_BUF);
    int b = n0 >> 10, hw0 = n0 & 1023;
    const float* xb = x + (size_t)b * DIM * HW + hw0;
    float rs = 0.f;
    for (int cc0 = 0; cc0 < 8; cc0++) {
        __syncthreads();
#pragma unroll
        for (int i = 0; i < 8; i++) {
            int idx = tid + i * 512, ci = idx >> 7, nn = idx & 127;
            sT[ci * 129 + nn] = xb[(cc0 * 32 + ci) * HW + nn];
        }
        __syncthreads();
#pragma unroll
        for (int i = 0; i < 4; i++) {
            int idx = tid + i * 512, nn = idx >> 4, cp = idx & 15;
            float f0 = sT[(2 * cp) * 129 + nn];
            float f1 = sT[(2 * cp + 1) * 129 + nn];
            __nv_bfloat16 h0 = __float2bfloat16_rn(f0);
            __nv_bfloat16 h1 = __float2bfloat16_rn(f1);
            sA[nn * SA_ST + cc0 * 16 + cp] =
                ((uint32_t)__bfloat16_as_ushort(h1) << 16) | __bfloat16_as_ushort(h0);
        }
        if (tid < 128) {   // exact sequential rowsq
#pragma unroll
            for (int c = 0; c < 32; c++) {
                float v = sT[c * 129 + tid];
                rs = __fadd_rn(rs, __fmul_rn(v, v));
            }
        }
    }
    __syncthreads();
    if (tid < 128) sAn[tid] = rs;

    // panel 1 -> buf1
    {
        const uint32_t* gsrc = g_epack + (size_t)128 * 128;
#pragma unroll
        for (int i = 0; i < 8; i++) {
            int seg = tid + i * 512, code = seg >> 5, j = seg & 31;
            cp16(smu + (uint32_t)(SB_OFF + SB_BUF + code * SA_ST + j * 4) * 4,
                 gsrc + code * 128 + j * 4);
        }
        CP_COMMIT();
    }

    for (int p = 0; p < 8; p++) {
        if (p < 7) CP_WAIT(1); else CP_WAIT(0);
        __syncthreads();
        const uint32_t* Bbuf = sm + SB_OFF + (p & 1) * SB_BUF;

        float acc[2][4][4];
#pragma unroll
        for (int mt = 0; mt < 2; mt++)
#pragma unroll
            for (int nt = 0; nt < 4; nt++)
#pragma unroll
                for (int e2 = 0; e2 < 4; e2++) acc[mt][nt][e2] = 0.f;

        const uint32_t* Ab = sA + (wm * 32 + g) * SA_ST;
        const uint32_t* Bb = Bbuf + (wn * 32 + g) * SA_ST;
#pragma unroll
        for (int ks = 0; ks < 16; ks++) {
            uint32_t a[2][4];
#pragma unroll
            for (int mt = 0; mt < 2; mt++) {
                const uint32_t* ap = Ab + mt * 16 * SA_ST + ks * 8 + tg;
                a[mt][0] = ap[0];
                a[mt][1] = ap[8 * SA_ST];
                a[mt][2] = ap[4];
                a[mt][3] = ap[8 * SA_ST + 4];
            }
#pragma unroll
            for (int nt = 0; nt < 4; nt++) {
                uint32_t b0 = Bb[nt * 8 * SA_ST + ks * 8 + tg];
                uint32_t b1 = Bb[nt * 8 * SA_ST + ks * 8 + tg + 4];
#pragma unroll
                for (int mt = 0; mt < 2; mt++) {
                    asm volatile(
                        "mma.sync.aligned.m16n8k16.row.col.f32.bf16.bf16.f32 "
                        "{%0,%1,%2,%3}, {%4,%5,%6,%7}, {%8,%9}, {%0,%1,%2,%3};"
                        : "+f"(acc[mt][nt][0]), "+f"(acc[mt][nt][1]),
                          "+f"(acc[mt][nt][2]), "+f"(acc[mt][nt][3])
                        : "r"(a[mt][0]), "r"(a[mt][1]), "r"(a[mt][2]), "r"(a[mt][3]),
                          "r"(b0), "r"(b1));
                }
            }
        }

        // ---- phase 1: per-(row,warp) min ----
        int kb = p * 128 + wn * 32 + 2 * tg;
        float bkv[4][2];
#pragma unroll
        for (int nt = 0; nt < 4; nt++) {
            bkv[nt][0] = sBk[kb + nt * 8];
            bkv[nt][1] = sBk[kb + nt * 8 + 1];
        }
        float mn[4] = {CUDART_INF_F, CUDART_INF_F, CUDART_INF_F, CUDART_INF_F};
#pragma unroll
        for (int mt = 0; mt < 2; mt++)
#pragma unroll
            for (int nt = 0; nt < 4; nt++) {
                float t0 = __fmaf_rn(-2.f, acc[mt][nt][0], bkv[nt][0]);
                float t1 = __fmaf_rn(-2.f, acc[mt][nt][1], bkv[nt][1]);
                float t2 = __fmaf_rn(-2.f, acc[mt][nt][2], bkv[nt][0]);
                float t3 = __fmaf_rn(-2.f, acc[mt][nt][3], bkv[nt][1]);
                mn[mt * 2]     = fminf(mn[mt * 2], fminf(t0, t1));
                mn[mt * 2 + 1] = fminf(mn[mt * 2 + 1], fminf(t2, t3));
            }
#pragma unroll
        for (int i = 0; i < 4; i++) {
            mn[i] = fminf(mn[i], __shfl_xor_sync(0xffffffffu, mn[i], 1));
            mn[i] = fminf(mn[i], __shfl_xor_sync(0xffffffffu, mn[i], 2));
        }
        if (tg == 0) {
#pragma unroll
            for (int mt = 0; mt < 2; mt++)
#pragma unroll
                for (int h = 0; h < 2; h++) {
                    int r = wm * 32 + mt * 16 + g + 8 * h;
                    sMnW[r * 4 + wn] = mn[mt * 2 + h];
                }
        }
        __syncthreads();

        // prefetch panel p+2
        if (p + 2 < 8) {
            const uint32_t* gsrc = g_epack + (size_t)(p + 2) * 128 * 128;
            uint32_t dst = smu + (uint32_t)(SB_OFF + (p & 1) * SB_BUF) * 4;
#pragma unroll
            for (int i = 0; i < 8; i++) {
                int seg = tid + i * 512, code = seg >> 5, j = seg & 31;
                cp16(dst + (uint32_t)(code * SA_ST + j * 4) * 4,
                     gsrc + code * 128 + j * 4);
            }
            CP_COMMIT();
        }

        // ---- phase 2: capture candidates vs global running best ----
        float thr[4];
#pragma unroll
        for (int mt = 0; mt < 2; mt++)
#pragma unroll
            for (int h = 0; h < 2; h++) {
                int r = wm * 32 + mt * 16 + g + 8 * h;
                float t4 = fminf(fminf(sMnW[r * 4 + 0], sMnW[r * 4 + 1]),
                                 fminf(sMnW[r * 4 + 2], sMnW[r * 4 + 3]));
                thr[mt * 2 + h] = fminf(sBest[r], t4);
            }
#pragma unroll
        for (int mt = 0; mt < 2; mt++)
#pragma unroll
            for (int nt = 0; nt < 4; nt++)
#pragma unroll
                for (int e2 = 0; e2 < 4; e2++) {
                    float t = __fmaf_rn(-2.f, acc[mt][nt][e2], bkv[nt][e2 & 1]);
                    int h = e2 >> 1;
                    if (t <= thr[mt * 2 + h] + MARGIN) {
                        int r = wm * 32 + mt * 16 + g + 8 * h;
                        int k = kb + nt * 8 + (e2 & 1);
                        int pos = atomicAdd(&sCnt[r], 1);
                        if (pos < CANDCAP) sCand[r * CANDCAP + pos] = (unsigned short)k;
                    }
                }
        __syncthreads();
        if (wn == 0 && tg == 0) {
#pragma unroll
            for (int mt = 0; mt < 2; mt++)
#pragma unroll
                for (int h = 0; h < 2; h++) {
                    int r = wm * 32 + mt * 16 + g + 8 * h;
                    sBest[r] = thr[mt * 2 + h];
                }
        }
    }
    __syncthreads();

    // ---- stage x slice into SMEM (B buffers dead): sX[c*129 + row], f32 ----
    float* sX = (float*)(sm + SB_OFF);   // 256*129 u32 = 33024 <= 33792 available
#pragma unroll 1
    for (int idx = tid; idx < DIM * 128; idx += 512) {
        int c = idx >> 7, nn = idx & 127;
        sX[c * 129 + nn] = xb[c * HW + nn];
    }
    __syncthreads();

    // ---- in-block exact rescore (R4's bit-exact chain) ----
    // x from SMEM (lanes on consecutive rr -> conflict-free); e via float4
    // (4x fewer LDG wavefronts; fmaf order within the chain unchanged).
    if (tid < 128) sKey[tid] = 0xFFFFFFFFFFFFFFFFull;
    __syncthreads();

    int rr = tid & 127, slot = tid >> 7;   // 4 slots per row
    int cnt = sCnt[rr];
    if (cnt <= CANDCAP) {
        float an = sAn[rr];
        for (int s = slot; s < cnt; s += 4) {
            int k = sCand[rr * CANDCAP + s];
            const float4* ep4 = (const float4*)(e + (size_t)k * DIM);
            float a = 0.f;
#pragma unroll 8
            for (int d4 = 0; d4 < 64; d4++) {
                float4 ev = ep4[d4];
                int d = d4 * 4;
                a = __fmaf_rn(sX[d * 129 + rr],       ev.x, a);
                a = __fmaf_rn(sX[(d + 1) * 129 + rr], ev.y, a);
                a = __fmaf_rn(sX[(d + 2) * 129 + rr], ev.z, a);
                a = __fmaf_rn(sX[(d + 3) * 129 + rr], ev.w, a);
            }
            float sc = __fsub_rn(__fadd_rn(an, sBk[k]), __fmul_rn(2.0f, a));
            atomicMin(&sKey[rr], mkkey(sc, k));
        }
    } else if (slot == 0) {
        int pidx = atomicAdd(&sOvf[0], 1);
        sOvf[1 + pidx] = rr;
    }
    __syncthreads();

    // overflow rows (rare at cap 32): one warp per row, full exact scan
    int novf = sOvf[0];
    for (int li = w; li < novf; li += 16) {
        int r2 = sOvf[1 + li];
        float an2 = sAn[r2];
        unsigned long long bk = 0xFFFFFFFFFFFFFFFFull;
        for (int k = lane; k < KCODES; k += 32) {
            const float4* ep4 = (const float4*)(e + (size_t)k * DIM);
            float a = 0.f;
#pragma unroll 8
            for (int d4 = 0; d4 < 64; d4++) {
                float4 ev = ep4[d4];
                int d = d4 * 4;
                a = __fmaf_rn(sX[d * 129 + r2],       ev.x, a);
                a = __fmaf_rn(sX[(d + 1) * 129 + r2], ev.y, a);
                a = __fmaf_rn(sX[(d + 2) * 129 + r2], ev.z, a);
                a = __fmaf_rn(sX[(d + 3) * 129 + r2], ev.w, a);
            }
            float sc = __fsub_rn(__fadd_rn(an2, sBk[k]), __fmul_rn(2.0f, a));
            unsigned long long kk = mkkey(sc, k);
            if (kk < bk) bk = kk;
        }
#pragma unroll
        for (int m = 16; m > 0; m >>= 1) {
            unsigned long long o = __shfl_xor_sync(0xffffffffu, bk, m);
            if (o < bk) bk = o;
        }
        if (lane == 0) sKey[r2] = bk;
    }
    __syncthreads();
    if (tid < 128) g_idx[n0 + tid] = (int)(sKey[tid] & 0xFFFFFFFFu);
}

// ---------------- fused outputs: quantized_st + one-hot encodings + loss ----
// 1024 blocks x 256 threads (32 rows per block).
// Phase A (quantized+loss): thread (sub,rowl) — lanes sweep rows -> coalesced.
// Phase B (encodings): warp-per-row — lanes sweep columns -> coalesced.
__global__ __launch_bounds__(256) void k_out(const float* __restrict__ x,
                                             const float* __restrict__ emb,
                                             float* __restrict__ out) {
    int rowl = threadIdx.x & 31, sub = threadIdx.x >> 5;
    int n = blockIdx.x * 32 + rowl;
    int b = n >> 10, hw = n & 1023;
    const float* xp = x + (size_t)b * DIM * HW + hw;
    float* qp = out + 1 + (size_t)b * DIM * HW + hw;
    int idx = g_idx[n];
    const float* ep = emb + (size_t)idx * DIM;
    double ssum = 0.0;
    int c0 = sub * 32;
#pragma unroll 4
    for (int i = 0; i < 32; i++) {
        int c = c0 + i;
        float in = xp[c * HW];
        float q  = ep[c];
        float d  = __fsub_rn(q, in);          // fl(q - in)
        float st = __fadd_rn(in, d);          // fl(in + d)
        qp[c * HW] = st;
        ssum += (double)__fmul_rn(d, d);
    }

    // ---- Phase B: one-hot encodings, warp-per-row coalesced ----
    int lane = rowl;
#pragma unroll
    for (int rr = 0; rr < 4; rr++) {
        int n2 = blockIdx.x * 32 + sub * 4 + rr;
        int idx2 = g_idx[n2];
        float* seg = out + 1 + (size_t)N_TOTAL * DIM + (size_t)n2 * KCODES;
        if (lane < 3) seg[lane] = 0.f;
        if (lane == 3) seg[1023] = 0.f;
        uint4* v4 = (uint4*)(seg + 3);
#pragma unroll
        for (int it = 0; it < 8; it++) {
            int i = it * 32 + lane;
            if (i < 255) v4[i] = make_uint4(0, 0, 0, 0);
        }
        __syncwarp();
        if (lane == 0) seg[idx2] = 1.0f;
    }

    __shared__ double sred[256];
    sred[threadIdx.x] = ssum;
    __syncthreads();
    for (int s = 128; s > 0; s >>= 1) {
        if (threadIdx.x < s) sred[threadIdx.x] += sred[threadIdx.x + s];
        __syncthreads();
    }
    if (threadIdx.x == 0) g_partial[blockIdx.x] = sred[0];
}

__global__ void k_loss(float* __restrict__ out) {
    __shared__ double sred[256];
    double a = 0.0;
#pragma unroll
    for (int i = 0; i < 4; i++) a += g_partial[threadIdx.x * 4 + i];
    sred[threadIdx.x] = a;
    __syncthreads();
    for (int s = 128; s > 0; s >>= 1) {
        if (threadIdx.x < s) sred[threadIdx.x] += sred[threadIdx.x + s];
        __syncthreads();
    }
    if (threadIdx.x == 0) {
        double m = sred[0] / (double)((long long)N_TOTAL * DIM);
        out[0] = (float)(m + 0.25 * m);
    }
}

extern "C" void kernel_launch(void* const* d_in, const int* in_sizes, int n_in,
                              void* d_out, int out_size) {
    const float* x = (const float*)d_in[0];
    const float* e = (const float*)d_in[1];
    if (n_in >= 2 && in_sizes[0] == KCODES * DIM && in_sizes[1] == N_TOTAL * DIM) {
        x = (const float*)d_in[1];
        e = (const float*)d_in[0];
    }
    float* out = (float*)d_out;

    cudaFuncSetAttribute(k_gemm, cudaFuncAttributeMaxDynamicSharedMemorySize, SMEM_BYTES);

    k_prep<<<32, 256>>>(e);
    k_gemm<<<N_TOTAL / 128, 512, SMEM_BYTES>>>(x, e);
    k_out<<<N_TOTAL / 32, 256>>>(x, e, out);
    k_loss<<<1, 256>>>(out);
}